// round 5
// baseline (speedup 1.0000x reference)
#include <cuda_runtime.h>

// ManagerStateTracker: B=1024, P=64, N=512, E=256, F=64
// out row (width 12800):
//   [0,64)       feasible_personal_info_nodes
//   [64,192)     workers_decision (P*2)
//   [192,4288)   known_one_hot (P*F)
//   [4288,8384)  unknown_one_hot
//   [8384,12480) known_differ_one_hot
//   [12480,12544) total_qa_turn_one_hot
//   [12544,12800) agg_state = mean_p tanh(embed[b, nodes[b,p], :] @ W + b)

#define BDIM 1024
#define PDIM 64
#define NDIM 512
#define EDIM 256
#define OUTW 12800
#define COPYW 12544
#define COPYW4 (COPYW / 4)   // 3136 float4 per row

typedef unsigned long long u64;

__device__ __forceinline__ void ffma2(u64& d, u64 a, u64 b) {
    // packed fp32x2 fused multiply-add: d = a*b + d (elementwise on 2 floats)
    asm("fma.rn.f32x2 %0, %1, %2, %0;" : "+l"(d) : "l"(a), "l"(b));
}
__device__ __forceinline__ u64 pack2(float x, float y) {
    u64 r; asm("mov.b64 %0, {%1, %2};" : "=l"(r) : "f"(x), "f"(y)); return r;
}
__device__ __forceinline__ void unpack2(u64 v, float& lo, float& hi) {
    asm("mov.b64 {%0, %1}, %2;" : "=f"(lo), "=f"(hi) : "l"(v));
}
__device__ __forceinline__ float tanh_fast(float x) {
    asm("tanh.approx.f32 %0, %0;" : "+f"(x)); return x;
}

// ---------------------------------------------------------------------------
// Fused kernel: one CTA per batch, 256 threads.
//   phase 1: gather X (transposed into smem: XsT[e][p], stride 64)
//   phase 2: k-tiled GEMM with packed f32x2 FMAs; tanh+mean epilogue
//   phase 3: concat copy for this batch (overlaps next wave's GEMM)
// smem: XsT 64KB + Ws 32KB = 96KB dynamic -> 2 CTAs/SM.
// ---------------------------------------------------------------------------
__global__ void __launch_bounds__(256, 2)
fused_kernel(const float* __restrict__ feas,
             const float* __restrict__ work,
             const float* __restrict__ known,
             const float* __restrict__ unknown,
             const float* __restrict__ differ,
             const float* __restrict__ qa,
             const int*   __restrict__ nodes32,   // int32 OR int64 (probed)
             const float* __restrict__ embed,     // (B, N, E)
             const float* __restrict__ W,         // (E, E) row-major [e][f]
             const float* __restrict__ bias,      // (E,)
             float* __restrict__ out) {
    extern __shared__ float sm[];
    float* XsT = sm;                 // [EDIM][PDIM], element (e,p) at e*64+p
    float* Ws  = sm + EDIM * PDIM;   // [32][EDIM]

    const int b = blockIdx.x;
    const int t = threadIdx.x;

    // ---- int64-vs-int32 probe for `nodes` (deterministic; same answer every CTA)
    // If the buffer is int64 (values 0..511), the high int32 of each element is 0.
    // If int32 (uniform 0..511), 64 consecutive odd words are all-zero with
    // probability (1/512)^64 ~ 0.
    __shared__ int flag_is32;
    if (t == 0) flag_is32 = 0;
    __syncthreads();
    if (t < 64 && nodes32[2 * t + 1] != 0) flag_is32 = 1;  // benign race
    __syncthreads();
    const bool is64 = (flag_is32 == 0);

    // ---- Phase 1: gather X transposed. thread t: p = t&63, e-chunk = t>>6 (64 e's)
    {
        const int p = t & 63;
        const int ec = t >> 6;                    // 0..3
        const int gi = b * PDIM + p;
        const int node = is64 ? nodes32[2 * gi] : nodes32[gi];
        const float4* src =
            reinterpret_cast<const float4*>(embed + ((size_t)b * NDIM + node) * EDIM)
            + ec * 16;
        #pragma unroll
        for (int i = 0; i < 16; i++) {
            float4 v = src[i];
            int e = ec * 64 + i * 4;
            // lanes in a warp have distinct p (mod 32) -> conflict-free STS
            XsT[(e + 0) * PDIM + p] = v.x;
            XsT[(e + 1) * PDIM + p] = v.y;
            XsT[(e + 2) * PDIM + p] = v.z;
            XsT[(e + 3) * PDIM + p] = v.w;
        }
    }
    __syncthreads();

    // ---- Phase 2: GEMM. Register tile: 8 p-pairs (16 p-rows) x 4 f per thread.
    const int fg = t & 63;          // 64 f-groups of 4
    const int pg = t >> 6;          // 4 p-groups of 16 (warp-uniform)
    const int f0 = fg * 4;
    const int p0 = pg * 16;

    u64 acc[8][4];
    #pragma unroll
    for (int pp = 0; pp < 8; pp++)
        #pragma unroll
        for (int j = 0; j < 4; j++) acc[pp][j] = 0ull;

    for (int k0 = 0; k0 < EDIM; k0 += 32) {
        // stage W k-tile [k0,k0+32) x [0,256): 2048 float4, 8 per thread
        const float4* wsrc = reinterpret_cast<const float4*>(W + k0 * EDIM);
        float4* wdst = reinterpret_cast<float4*>(Ws);
        #pragma unroll
        for (int j = 0; j < 8; j++) wdst[t + j * 256] = wsrc[t + j * 256];
        __syncthreads();

        #pragma unroll 4
        for (int e = 0; e < 32; e++) {
            float4 w = *reinterpret_cast<const float4*>(Ws + e * EDIM + f0);
            u64 wp0 = pack2(w.x, w.x);
            u64 wp1 = pack2(w.y, w.y);
            u64 wp2 = pack2(w.z, w.z);
            u64 wp3 = pack2(w.w, w.w);
            const u64* xrow =
                reinterpret_cast<const u64*>(XsT + (k0 + e) * PDIM + p0);
            #pragma unroll
            for (int pp = 0; pp < 8; pp++) {
                u64 xp = xrow[pp];          // (x[p0+2pp], x[p0+2pp+1]) broadcast LDS.64
                ffma2(acc[pp][0], xp, wp0);
                ffma2(acc[pp][1], xp, wp1);
                ffma2(acc[pp][2], xp, wp2);
                ffma2(acc[pp][3], xp, wp3);
            }
        }
        __syncthreads();
    }

    // ---- Epilogue: tanh(. + bias), partial sum over this thread's 16 p-rows
    float4 bv = *reinterpret_cast<const float4*>(bias + f0);
    float s0 = 0.f, s1 = 0.f, s2 = 0.f, s3 = 0.f;
    #pragma unroll
    for (int pp = 0; pp < 8; pp++) {
        float lo, hi;
        unpack2(acc[pp][0], lo, hi); s0 += tanh_fast(lo + bv.x) + tanh_fast(hi + bv.x);
        unpack2(acc[pp][1], lo, hi); s1 += tanh_fast(lo + bv.y) + tanh_fast(hi + bv.y);
        unpack2(acc[pp][2], lo, hi); s2 += tanh_fast(lo + bv.z) + tanh_fast(hi + bv.z);
        unpack2(acc[pp][3], lo, hi); s3 += tanh_fast(lo + bv.w) + tanh_fast(hi + bv.w);
    }

    // cross-pg reduction in smem (reuse Ws; last loop iter ended with a sync)
    float* red = Ws;                 // 4 * 256 floats
    red[pg * EDIM + f0 + 0] = s0;
    red[pg * EDIM + f0 + 1] = s1;
    red[pg * EDIM + f0 + 2] = s2;
    red[pg * EDIM + f0 + 3] = s3;
    __syncthreads();

    float s = red[t] + red[EDIM + t] + red[2 * EDIM + t] + red[3 * EDIM + t];
    out[(size_t)b * OUTW + COPYW + t] = s * (1.0f / (float)PDIM);

    // ---- Phase 3: concat copy for this batch (3136 float4, 256 threads)
    float* orow = out + (size_t)b * OUTW;
    #pragma unroll 2
    for (int i = t; i < COPYW4; i += 256) {
        int c = i * 4;
        const float* src;
        if (c < 64)          src = feas    + b * 64   + c;
        else if (c < 192)    src = work    + b * 128  + (c - 64);
        else if (c < 4288)   src = known   + b * 4096 + (c - 192);
        else if (c < 8384)   src = unknown + b * 4096 + (c - 4288);
        else if (c < 12480)  src = differ  + b * 4096 + (c - 8384);
        else                 src = qa      + b * 64   + (c - 12480);
        *reinterpret_cast<float4*>(orow + c) =
            *reinterpret_cast<const float4*>(src);
    }
}

// ---------------------------------------------------------------------------
extern "C" void kernel_launch(void* const* d_in, const int* in_sizes, int n_in,
                              void* d_out, int out_size) {
    const float* feas    = (const float*)d_in[0];
    const float* work    = (const float*)d_in[1];
    const float* known   = (const float*)d_in[2];
    const float* unknown = (const float*)d_in[3];
    const float* differ  = (const float*)d_in[4];
    const float* qa      = (const float*)d_in[5];
    const int*   nodes   = (const int*)d_in[6];
    const float* embed   = (const float*)d_in[7];
    const float* W       = (const float*)d_in[8];
    const float* bias    = (const float*)d_in[9];
    float* out = (float*)d_out;

    const int smem_bytes = (EDIM * PDIM + 32 * EDIM) * sizeof(float);  // 96KB
    static bool attr_set = false;
    if (!attr_set) {
        cudaFuncSetAttribute(fused_kernel,
                             cudaFuncAttributeMaxDynamicSharedMemorySize, smem_bytes);
        attr_set = true;
    }

    fused_kernel<<<BDIM, 256, smem_bytes>>>(
        feas, work, known, unknown, differ, qa, nodes, embed, W, bias, out);
}

// round 6
// speedup vs baseline: 1.5507x; 1.5507x over previous
#include <cuda_runtime.h>
#include <cuda_bf16.h>

// ManagerStateTracker: B=1024, P=64, N=512, E=256, F=64
// out row (width 12800):
//   [0,12544)     concat of 6 contiguous per-batch blocks
//   [12544,12800) agg_state = mean_p tanh(embed[b, nodes[b,p], :] @ W + b)

#define BDIM 1024
#define PDIM 64
#define NDIM 512
#define EDIM 256
#define OUTW 12800
#define COPYW 12544
#define COPYW4 (COPYW / 4)   // 3136 float4 per row

#define XPAD 264             // X smem row pitch (bf16): 528B -> 4-bank skew, conflict-free frags
#define WPAD 72              // Wt smem row pitch (bf16): 144B -> 4-bank skew, conflict-free frags

// W transposed+converted to bf16, [n][k] layout (n-major). 128KB device global.
__device__ __nv_bfloat16 g_Wt[EDIM * EDIM];

__device__ __forceinline__ float tanh_fast(float x) {
    asm("tanh.approx.f32 %0, %0;" : "+f"(x)); return x;
}

__device__ __forceinline__ void mma_bf16(float& d0, float& d1, float& d2, float& d3,
                                         unsigned a0, unsigned a1, unsigned a2, unsigned a3,
                                         unsigned b0, unsigned b1) {
    asm("mma.sync.aligned.m16n8k16.row.col.f32.bf16.bf16.f32 "
        "{%0,%1,%2,%3}, {%4,%5,%6,%7}, {%8,%9}, {%0,%1,%2,%3};"
        : "+f"(d0), "+f"(d1), "+f"(d2), "+f"(d3)
        : "r"(a0), "r"(a1), "r"(a2), "r"(a3), "r"(b0), "r"(b1));
}

// ---------------------------------------------------------------------------
// Kernel 0: W (E,E) fp32 [k][n] -> g_Wt bf16 [n][k]
// ---------------------------------------------------------------------------
__global__ void wconv_kernel(const float* __restrict__ W) {
    int idx = blockIdx.x * blockDim.x + threadIdx.x;   // 65536
    int n = idx >> 8;
    int k = idx & 255;
    g_Wt[n * EDIM + k] = __float2bfloat16(W[k * EDIM + n]);
}

// ---------------------------------------------------------------------------
// Kernel 1: fused per-batch gather + bf16 HMMA GEMM + tanh/mean + concat copy
// One CTA per batch, 256 threads (8 warps). Warp w: full M=64, n-slice [32w,32w+32).
// smem: Xs[64][XPAD] bf16 (33KB) + Wsm[256][WPAD] bf16 (36KB) = 70.6KB -> 2 CTAs/SM
// ---------------------------------------------------------------------------
__global__ void __launch_bounds__(256, 2)
fused_kernel(const float* __restrict__ feas,
             const float* __restrict__ work,
             const float* __restrict__ known,
             const float* __restrict__ unknown,
             const float* __restrict__ differ,
             const float* __restrict__ qa,
             const int*   __restrict__ nodes32,   // int32 OR int64 (probed)
             const float* __restrict__ embed,     // (B, N, E)
             const float* __restrict__ bias,      // (E,)
             float* __restrict__ out) {
    extern __shared__ char smraw[];
    __nv_bfloat16* Xs  = reinterpret_cast<__nv_bfloat16*>(smraw);             // [64][XPAD]
    __nv_bfloat16* Wsm = Xs + PDIM * XPAD;                                    // [256][WPAD]

    const int b = blockIdx.x;
    const int t = threadIdx.x;

    // ---- int64-vs-int32 probe (deterministic: P(false pos) = (1/512)^64 ~ 0)
    __shared__ int flag_is32;
    if (t == 0) flag_is32 = 0;
    __syncthreads();
    if (t < 64 && nodes32[2 * t + 1] != 0) flag_is32 = 1;  // benign race
    __syncthreads();
    const bool is64 = (flag_is32 == 0);

    // ---- Phase 1: gather X rows, convert fp32->bf16 into Xs
    // thread t: row p = t>>2, quarter q = t&3 (cols q*64..q*64+63)
    {
        const int p = t >> 2;
        const int q = t & 3;
        const int gi = b * PDIM + p;
        const int node = is64 ? nodes32[2 * gi] : nodes32[gi];
        const float4* src =
            reinterpret_cast<const float4*>(embed + ((size_t)b * NDIM + node) * EDIM)
            + q * 16;
        __nv_bfloat16* drow = Xs + p * XPAD + q * 64;
        #pragma unroll
        for (int i = 0; i < 16; i++) {
            float4 v = src[i];
            __nv_bfloat162 lo = __floats2bfloat162_rn(v.x, v.y);
            __nv_bfloat162 hi = __floats2bfloat162_rn(v.z, v.w);
            // 8B store, 8B-aligned (XPAD*2=528, q*128, i*8 all 8B-multiples)
            reinterpret_cast<uint2*>(drow + i * 4)[0] =
                make_uint2(*reinterpret_cast<unsigned*>(&lo),
                           *reinterpret_cast<unsigned*>(&hi));
        }
    }
    __syncthreads();

    // ---- Phase 2: GEMM via mma.sync m16n8k16 bf16
    const int warp = t >> 5;
    const int lane = t & 31;
    const int g    = lane >> 2;    // group id (0..7)
    const int t4   = lane & 3;     // thread in group
    const int nb   = warp * 32;    // warp's n-slice base

    float acc[4][4][4];            // [m-tile][n-tile][c0..c3], zero
    #pragma unroll
    for (int mt = 0; mt < 4; mt++)
        #pragma unroll
        for (int nt = 0; nt < 4; nt++)
            #pragma unroll
            for (int j = 0; j < 4; j++) acc[mt][nt][j] = 0.0f;

    for (int kt = 0; kt < 4; kt++) {               // k-tiles of 64
        // stage Wt k-tile: thread t copies row n=t, 128B (8 x uint4)
        {
            const uint4* src = reinterpret_cast<const uint4*>(g_Wt + t * EDIM + kt * 64);
            uint4* dst = reinterpret_cast<uint4*>(Wsm + t * WPAD);
            #pragma unroll
            for (int j = 0; j < 8; j++) dst[j] = src[j];
        }
        __syncthreads();

        #pragma unroll
        for (int ks = 0; ks < 4; ks++) {           // k-steps of 16
            const int k0 = ks * 16;
            // B fragments for the 4 n-tiles
            unsigned b0[4], b1[4];
            #pragma unroll
            for (int nt = 0; nt < 4; nt++) {
                const __nv_bfloat16* row = Wsm + (nb + nt * 8 + g) * WPAD + k0 + 2 * t4;
                b0[nt] = *reinterpret_cast<const unsigned*>(row);
                b1[nt] = *reinterpret_cast<const unsigned*>(row + 8);
            }
            #pragma unroll
            for (int mt = 0; mt < 4; mt++) {
                const __nv_bfloat16* xa = Xs + (mt * 16 + g) * XPAD + kt * 64 + k0 + 2 * t4;
                const __nv_bfloat16* xb = xa + 8 * XPAD;
                unsigned a0 = *reinterpret_cast<const unsigned*>(xa);
                unsigned a2 = *reinterpret_cast<const unsigned*>(xa + 8);
                unsigned a1 = *reinterpret_cast<const unsigned*>(xb);
                unsigned a3 = *reinterpret_cast<const unsigned*>(xb + 8);
                #pragma unroll
                for (int nt = 0; nt < 4; nt++)
                    mma_bf16(acc[mt][nt][0], acc[mt][nt][1], acc[mt][nt][2], acc[mt][nt][3],
                             a0, a1, a2, a3, b0[nt], b1[nt]);
            }
        }
        __syncthreads();
    }

    // ---- Epilogue: tanh(. + bias), sum over M, cross-group shfl reduce
    // Lane's output cols per nt: c = nb + nt*8 + 2*t4 + {0,1}; rows covered: mt*16+g, +8.
    float s0[4], s1[4];
    #pragma unroll
    for (int nt = 0; nt < 4; nt++) {
        const int c = nb + nt * 8 + 2 * t4;
        const float bz0 = __ldg(bias + c);
        const float bz1 = __ldg(bias + c + 1);
        float a = 0.f, bsum = 0.f;
        #pragma unroll
        for (int mt = 0; mt < 4; mt++) {
            a    += tanh_fast(acc[mt][nt][0] + bz0) + tanh_fast(acc[mt][nt][2] + bz0);
            bsum += tanh_fast(acc[mt][nt][1] + bz1) + tanh_fast(acc[mt][nt][3] + bz1);
        }
        s0[nt] = a; s1[nt] = bsum;
    }
    #pragma unroll
    for (int off = 4; off <= 16; off <<= 1) {      // reduce over g (lane bits 2..4)
        #pragma unroll
        for (int nt = 0; nt < 4; nt++) {
            s0[nt] += __shfl_xor_sync(0xffffffffu, s0[nt], off);
            s1[nt] += __shfl_xor_sync(0xffffffffu, s1[nt], off);
        }
    }
    if (g == 0) {                                  // lanes 0..3 hold full column sums
        float* orow = out + (size_t)b * OUTW + COPYW;
        #pragma unroll
        for (int nt = 0; nt < 4; nt++) {
            const int c = nb + nt * 8 + 2 * t4;
            orow[c]     = s0[nt] * (1.0f / (float)PDIM);
            orow[c + 1] = s1[nt] * (1.0f / (float)PDIM);
        }
    }

    // ---- Phase 3: concat copy for this batch (3136 float4, 256 threads)
    float* orow = out + (size_t)b * OUTW;
    #pragma unroll 2
    for (int i = t; i < COPYW4; i += 256) {
        int c = i * 4;
        const float* src;
        if (c < 64)          src = feas    + b * 64   + c;
        else if (c < 192)    src = work    + b * 128  + (c - 64);
        else if (c < 4288)   src = known   + b * 4096 + (c - 192);
        else if (c < 8384)   src = unknown + b * 4096 + (c - 4288);
        else if (c < 12480)  src = differ  + b * 4096 + (c - 8384);
        else                 src = qa      + b * 64   + (c - 12480);
        *reinterpret_cast<float4*>(orow + c) =
            *reinterpret_cast<const float4*>(src);
    }
}

// ---------------------------------------------------------------------------
extern "C" void kernel_launch(void* const* d_in, const int* in_sizes, int n_in,
                              void* d_out, int out_size) {
    const float* feas    = (const float*)d_in[0];
    const float* work    = (const float*)d_in[1];
    const float* known   = (const float*)d_in[2];
    const float* unknown = (const float*)d_in[3];
    const float* differ  = (const float*)d_in[4];
    const float* qa      = (const float*)d_in[5];
    const int*   nodes   = (const int*)d_in[6];
    const float* embed   = (const float*)d_in[7];
    const float* W       = (const float*)d_in[8];
    const float* bias    = (const float*)d_in[9];
    float* out = (float*)d_out;

    const int smem_bytes = (PDIM * XPAD + EDIM * WPAD) * sizeof(__nv_bfloat16); // 70656
    static bool attr_set = false;
    if (!attr_set) {
        cudaFuncSetAttribute(fused_kernel,
                             cudaFuncAttributeMaxDynamicSharedMemorySize, smem_bytes);
        attr_set = true;
    }

    wconv_kernel<<<EDIM * EDIM / 256, 256>>>(W);
    fused_kernel<<<BDIM, 256, smem_bytes>>>(
        feas, work, known, unknown, differ, qa, nodes, embed, bias, out);
}

// round 8
// speedup vs baseline: 2.3827x; 1.5366x over previous
#include <cuda_runtime.h>
#include <cuda_bf16.h>

// ManagerStateTracker: B=1024, P=64, N=512, E=256, F=64
// out row (width 12800):
//   [0,64)        feasible   [64,192) workers   [192,4288) known
//   [4288,8384)   unknown    [8384,12480) differ [12480,12544) qa
//   [12544,12800) agg_state = mean_p tanh(embed[b, nodes[b,p], :] @ W + b)

#define BDIM 1024
#define PDIM 64
#define NDIM 512
#define EDIM 256
#define OUTW 12800
#define COPYW 12544

#define XPAD 264   // X smem pitch (bf16): 528B = 33*16B -> conflict-free ldmatrix

// W transposed+converted to bf16, [n][k]. 128KB, L2/L1-resident.
__device__ __nv_bfloat16 g_Wt[EDIM * EDIM];

__device__ __forceinline__ float tanh_fast(float x) {
    asm("tanh.approx.f32 %0, %0;" : "+f"(x)); return x;
}

__device__ __forceinline__ void mma_bf16(float& d0, float& d1, float& d2, float& d3,
                                         unsigned a0, unsigned a1, unsigned a2, unsigned a3,
                                         unsigned b0, unsigned b1) {
    asm("mma.sync.aligned.m16n8k16.row.col.f32.bf16.bf16.f32 "
        "{%0,%1,%2,%3}, {%4,%5,%6,%7}, {%8,%9}, {%0,%1,%2,%3};"
        : "+f"(d0), "+f"(d1), "+f"(d2), "+f"(d3)
        : "r"(a0), "r"(a1), "r"(a2), "r"(a3), "r"(b0), "r"(b1));
}

__device__ __forceinline__ void ldsm_x4(unsigned& r0, unsigned& r1,
                                        unsigned& r2, unsigned& r3, const void* p) {
    unsigned addr = (unsigned)__cvta_generic_to_shared(p);
    asm volatile("ldmatrix.sync.aligned.m8n8.x4.shared.b16 {%0,%1,%2,%3}, [%4];"
                 : "=r"(r0), "=r"(r1), "=r"(r2), "=r"(r3) : "r"(addr));
}

// ---------------------------------------------------------------------------
// Kernel 0: W (E,E) fp32 [k][n] -> g_Wt bf16 [n][k]
// ---------------------------------------------------------------------------
__global__ void wconv_kernel(const float* __restrict__ W) {
    int idx = blockIdx.x * blockDim.x + threadIdx.x;   // 65536
    int n = idx >> 8;
    int k = idx & 255;
    g_Wt[n * EDIM + k] = __float2bfloat16(W[k * EDIM + n]);
}

// ---------------------------------------------------------------------------
// Kernel 1: fused gather + HMMA GEMM (B-frags straight from L2) + tanh/mean
//           + concat copy. ONE __syncthreads total.
// One CTA per batch, 256 threads (8 warps). Warp w: n-slice [32w, 32w+32).
// smem: Xs[64][XPAD] bf16 = 33KB.
// ---------------------------------------------------------------------------
__global__ void __launch_bounds__(256, 2)
fused_kernel(const float* __restrict__ feas,
             const float* __restrict__ work,
             const float* __restrict__ known,
             const float* __restrict__ unknown,
             const float* __restrict__ differ,
             const float* __restrict__ qa,
             const int*   __restrict__ nodes32,   // int32 OR int64 (probed)
             const float* __restrict__ embed,     // (B, N, E)
             const float* __restrict__ bias,      // (E,)
             float* __restrict__ out) {
    extern __shared__ char smraw[];
    __nv_bfloat16* Xs = reinterpret_cast<__nv_bfloat16*>(smraw);  // [64][XPAD]

    const int b    = blockIdx.x;
    const int t    = threadIdx.x;
    const int lane = t & 31;

    // ---- int64 probe, per-warp, barrier-free.
    // Read the first 32 candidate high-words; if dtype is int64 (values<512)
    // they are ALL zero. P(false positive for int32) = (1/512)^32 ~ 0.
    const bool is64 =
        (__ballot_sync(0xffffffffu, nodes32[2 * lane + 1] != 0) == 0u);

    // ---- Phase 1: gather X rows, fp32 -> bf16 into Xs.
    // thread t: row p = t>>2, quarter q = t&3 (64 cols). 16 batched LDG.128.
    {
        const int p = t >> 2;
        const int q = t & 3;
        const int gi = b * PDIM + p;
        const int node = is64 ? nodes32[2 * gi] : nodes32[gi];
        const float4* src =
            reinterpret_cast<const float4*>(embed + ((size_t)b * NDIM + node) * EDIM)
            + q * 16;
        __nv_bfloat16* drow = Xs + p * XPAD + q * 64;
        #pragma unroll
        for (int i = 0; i < 16; i++) {
            float4 v = src[i];
            __nv_bfloat162 lo = __floats2bfloat162_rn(v.x, v.y);
            __nv_bfloat162 hi = __floats2bfloat162_rn(v.z, v.w);
            reinterpret_cast<uint2*>(drow + i * 4)[0] =
                make_uint2(*reinterpret_cast<unsigned*>(&lo),
                           *reinterpret_cast<unsigned*>(&hi));
        }
    }
    __syncthreads();   // the ONLY barrier

    // ---- Phase 2: GEMM. B-fragments via LDG.32 from g_Wt (L2/L1-hot).
    const int warp = t >> 5;
    const int g    = lane >> 2;    // 0..7
    const int t4   = lane & 3;     // 0..3
    const int nb   = warp * 32;    // warp n-slice base
    const int lrow = lane & 15;    // ldmatrix row within m16 tile
    const int lcol = (lane >> 4) * 8;

    float acc[4][4][4];
    #pragma unroll
    for (int mt = 0; mt < 4; mt++)
        #pragma unroll
        for (int nt = 0; nt < 4; nt++)
            #pragma unroll
            for (int j = 0; j < 4; j++) acc[mt][nt][j] = 0.0f;

    #pragma unroll
    for (int kt = 0; kt < 4; kt++) {
        #pragma unroll
        for (int ks = 0; ks < 4; ks++) {
            const int k0 = kt * 64 + ks * 16;
            // B frags (straight from global; rows identical across CTAs -> L1 hit)
            unsigned b0[4], b1[4];
            #pragma unroll
            for (int nt = 0; nt < 4; nt++) {
                const __nv_bfloat16* row = g_Wt + (nb + nt * 8 + g) * EDIM + k0 + 2 * t4;
                b0[nt] = __ldg(reinterpret_cast<const unsigned*>(row));
                b1[nt] = __ldg(reinterpret_cast<const unsigned*>(row + 8));
            }
            #pragma unroll
            for (int mt = 0; mt < 4; mt++) {
                unsigned a0, a1, a2, a3;
                ldsm_x4(a0, a1, a2, a3,
                        Xs + (mt * 16 + lrow) * XPAD + k0 + lcol);
                #pragma unroll
                for (int nt = 0; nt < 4; nt++)
                    mma_bf16(acc[mt][nt][0], acc[mt][nt][1],
                             acc[mt][nt][2], acc[mt][nt][3],
                             a0, a1, a2, a3, b0[nt], b1[nt]);
            }
        }
    }

    // ---- Epilogue: tanh(.+bias), sum over M, shfl-reduce over g.
    float s0[4], s1[4];
    #pragma unroll
    for (int nt = 0; nt < 4; nt++) {
        const int c = nb + nt * 8 + 2 * t4;
        const float bz0 = __ldg(bias + c);
        const float bz1 = __ldg(bias + c + 1);
        float a = 0.f, bsum = 0.f;
        #pragma unroll
        for (int mt = 0; mt < 4; mt++) {
            a    += tanh_fast(acc[mt][nt][0] + bz0) + tanh_fast(acc[mt][nt][2] + bz0);
            bsum += tanh_fast(acc[mt][nt][1] + bz1) + tanh_fast(acc[mt][nt][3] + bz1);
        }
        s0[nt] = a; s1[nt] = bsum;
    }
    #pragma unroll
    for (int off = 4; off <= 16; off <<= 1) {
        #pragma unroll
        for (int nt = 0; nt < 4; nt++) {
            s0[nt] += __shfl_xor_sync(0xffffffffu, s0[nt], off);
            s1[nt] += __shfl_xor_sync(0xffffffffu, s1[nt], off);
        }
    }
    if (g == 0) {
        float* orow = out + (size_t)b * OUTW + COPYW;
        #pragma unroll
        for (int nt = 0; nt < 4; nt++) {
            const int c = nb + nt * 8 + 2 * t4;
            orow[c]     = s0[nt] * (1.0f / (float)PDIM);
            orow[c + 1] = s1[nt] * (1.0f / (float)PDIM);
        }
    }

    // ---- Phase 3: concat copy, MLP=12.
    // Big blocks (known/unknown/differ): 3 x 1024 float4 = 3072 = 12 per thread.
    {
        float* orow = out + (size_t)b * OUTW;
        const float* bsrc[3] = { known   + b * 4096,
                                 unknown + b * 4096,
                                 differ  + b * 4096 };
        float4 v[12];
        #pragma unroll
        for (int j = 0; j < 12; j++) {
            int idx = t + j * 256;              // 0..3071
            int blk = idx >> 10;
            int off = idx & 1023;               // float4 index within block
            v[j] = reinterpret_cast<const float4*>(bsrc[blk])[off];
        }
        #pragma unroll
        for (int j = 0; j < 12; j++) {
            int idx = t + j * 256;
            int blk = idx >> 10;
            int off = idx & 1023;
            reinterpret_cast<float4*>(orow + 192 + blk * 4096)[off] = v[j];
        }
        // Small blocks: feas(16 f4 @0) + work(32 f4 @64) + qa(16 f4 @12480)
        if (t < 64) {
            const float* src;
            int c;
            if (t < 16)      { src = feas + b * 64  + 4 * t;        c = 4 * t; }
            else if (t < 48) { src = work + b * 128 + 4 * (t - 16); c = 64 + 4 * (t - 16); }
            else             { src = qa   + b * 64  + 4 * (t - 48); c = 12480 + 4 * (t - 48); }
            *reinterpret_cast<float4*>(orow + c) =
                *reinterpret_cast<const float4*>(src);
        }
    }
}

// ---------------------------------------------------------------------------
extern "C" void kernel_launch(void* const* d_in, const int* in_sizes, int n_in,
                              void* d_out, int out_size) {
    const float* feas    = (const float*)d_in[0];
    const float* work    = (const float*)d_in[1];
    const float* known   = (const float*)d_in[2];
    const float* unknown = (const float*)d_in[3];
    const float* differ  = (const float*)d_in[4];
    const float* qa      = (const float*)d_in[5];
    const int*   nodes   = (const int*)d_in[6];
    const float* embed   = (const float*)d_in[7];
    const float* W       = (const float*)d_in[8];
    const float* bias    = (const float*)d_in[9];
    float* out = (float*)d_out;

    const int smem_bytes = PDIM * XPAD * sizeof(__nv_bfloat16);   // 33792 < 48KB

    wconv_kernel<<<EDIM * EDIM / 256, 256>>>(W);
    fused_kernel<<<BDIM, 256, smem_bytes>>>(
        feas, work, known, unknown, differ, qa, nodes, embed, bias, out);
}

// round 9
// speedup vs baseline: 4.2258x; 1.7735x over previous
#include <cuda_runtime.h>
#include <cuda_bf16.h>

// ManagerStateTracker: B=1024, P=64, N=512, E=256, F=64
// out row (width 12800):
//   [0,64) feas  [64,192) work  [192,4288) known  [4288,8384) unknown
//   [8384,12480) differ  [12480,12544) qa
//   [12544,12800) agg_state = mean_p tanh(embed[b, nodes[b,p], :] @ W + b)

#define BDIM 1024
#define PDIM 64
#define NDIM 512
#define EDIM 256
#define OUTW 12800
#define COPYW 12544

#define XPAD 264   // X smem pitch (bf16): 528B = 33*16B -> conflict-free ldmatrix

// W pre-packed into mma B-fragment order:
// g_Wfrag[w(8)][kstep(16)][nt(4)][lane(32)] = uint2{b0, b1}
//   where b0 = bf16x2( W[k0+2t4][n], W[k0+2t4+1][n] ),
//         b1 = bf16x2( W[k0+8+2t4][n], W[k0+9+2t4][n] ),
//   n = w*32 + nt*8 + (lane>>2), k0 = kstep*16, t4 = lane&3.
// One LDG.64 per (kstep,nt): 256B contiguous per warp -> 2 wavefronts.
__device__ uint2 g_Wfrag[8 * 16 * 4 * 32];   // 128KB

__device__ __forceinline__ float tanh_fast(float x) {
    asm("tanh.approx.f32 %0, %0;" : "+f"(x)); return x;
}

__device__ __forceinline__ void mma_bf16(float& d0, float& d1, float& d2, float& d3,
                                         unsigned a0, unsigned a1, unsigned a2, unsigned a3,
                                         unsigned b0, unsigned b1) {
    asm("mma.sync.aligned.m16n8k16.row.col.f32.bf16.bf16.f32 "
        "{%0,%1,%2,%3}, {%4,%5,%6,%7}, {%8,%9}, {%0,%1,%2,%3};"
        : "+f"(d0), "+f"(d1), "+f"(d2), "+f"(d3)
        : "r"(a0), "r"(a1), "r"(a2), "r"(a3), "r"(b0), "r"(b1));
}

__device__ __forceinline__ void ldsm_x4(unsigned& r0, unsigned& r1,
                                        unsigned& r2, unsigned& r3, const void* p) {
    unsigned addr = (unsigned)__cvta_generic_to_shared(p);
    asm volatile("ldmatrix.sync.aligned.m8n8.x4.shared.b16 {%0,%1,%2,%3}, [%4];"
                 : "=r"(r0), "=r"(r1), "=r"(r2), "=r"(r3) : "r"(addr));
}

// ---------------------------------------------------------------------------
// Kernel 0: W (E,E) fp32 [k][n] -> fragment-packed bf16 g_Wfrag
// ---------------------------------------------------------------------------
__global__ void wconv_kernel(const float* __restrict__ W) {
    int idx = blockIdx.x * blockDim.x + threadIdx.x;   // 16384 slots
    int lane = idx & 31;
    int nt   = (idx >> 5) & 3;
    int ks   = (idx >> 7) & 15;
    int w    = idx >> 11;
    int g  = lane >> 2;
    int t4 = lane & 3;
    int n  = w * 32 + nt * 8 + g;
    int k0 = ks * 16 + 2 * t4;
    __nv_bfloat162 lo = __floats2bfloat162_rn(W[(k0)     * EDIM + n],
                                              W[(k0 + 1) * EDIM + n]);
    __nv_bfloat162 hi = __floats2bfloat162_rn(W[(k0 + 8) * EDIM + n],
                                              W[(k0 + 9) * EDIM + n]);
    g_Wfrag[idx] = make_uint2(*reinterpret_cast<unsigned*>(&lo),
                              *reinterpret_cast<unsigned*>(&hi));
}

// ---------------------------------------------------------------------------
// Kernel 1: fused gather + concat copy + HMMA GEMM + tanh/mean.
// One CTA per batch, 256 threads (8 warps). Warp w: n-slice [32w, 32w+32).
// ONE __syncthreads; copy runs before it to fill the gather-latency window.
// smem: Xs[64][XPAD] bf16 = 33KB.
// ---------------------------------------------------------------------------
__global__ void __launch_bounds__(256, 2)
fused_kernel(const float* __restrict__ feas,
             const float* __restrict__ work,
             const float* __restrict__ known,
             const float* __restrict__ unknown,
             const float* __restrict__ differ,
             const float* __restrict__ qa,
             const int*   __restrict__ nodes32,   // int32 OR int64 (probed)
             const float* __restrict__ embed,     // (B, N, E)
             const float* __restrict__ bias,      // (E,)
             float* __restrict__ out) {
    extern __shared__ char smraw[];
    __nv_bfloat16* Xs = reinterpret_cast<__nv_bfloat16*>(smraw);  // [64][XPAD]

    const int b    = blockIdx.x;
    const int t    = threadIdx.x;
    const int lane = t & 31;
    const int warp = t >> 5;

    // ---- int64 probe, per-warp, barrier-free.
    // If dtype is int64 (values < 512) all high words are 0.
    // P(false positive for random int32 in [0,512)) = (1/512)^32 ~ 0.
    const bool is64 =
        (__ballot_sync(0xffffffffu, nodes32[2 * lane + 1] != 0) == 0u);

    // ---- Phase 1: gather X rows 8w..8w+7, row-contiguous (nL=4 per LDG.128).
    {
        const int gi0 = b * PDIM + warp * 8;
        int myn = 0;
        if (lane < 8)
            myn = is64 ? nodes32[2 * (gi0 + lane)] : nodes32[gi0 + lane];
        #pragma unroll
        for (int r = 0; r < 8; r++) {
            const int node = __shfl_sync(0xffffffffu, myn, r);
            const float4* src =
                reinterpret_cast<const float4*>(embed + ((size_t)b * NDIM + node) * EDIM);
            float4 v0 = src[lane];
            float4 v1 = src[lane + 32];
            __nv_bfloat162 a0 = __floats2bfloat162_rn(v0.x, v0.y);
            __nv_bfloat162 a1 = __floats2bfloat162_rn(v0.z, v0.w);
            __nv_bfloat162 c0 = __floats2bfloat162_rn(v1.x, v1.y);
            __nv_bfloat162 c1 = __floats2bfloat162_rn(v1.z, v1.w);
            __nv_bfloat16* drow = Xs + (warp * 8 + r) * XPAD;
            reinterpret_cast<uint2*>(drow + lane * 4)[0] =
                make_uint2(*reinterpret_cast<unsigned*>(&a0),
                           *reinterpret_cast<unsigned*>(&a1));
            reinterpret_cast<uint2*>(drow + 128 + lane * 4)[0] =
                make_uint2(*reinterpret_cast<unsigned*>(&c0),
                           *reinterpret_cast<unsigned*>(&c1));
        }
    }

    // ---- Phase 2: concat copy (independent of GEMM; fills barrier window).
    {
        float* orow = out + (size_t)b * OUTW;
        const float* bsrc[3] = { known   + b * 4096,
                                 unknown + b * 4096,
                                 differ  + b * 4096 };
        float4 v[12];
        #pragma unroll
        for (int j = 0; j < 12; j++) {
            int idx = t + j * 256;              // 0..3071
            v[j] = reinterpret_cast<const float4*>(bsrc[idx >> 10])[idx & 1023];
        }
        #pragma unroll
        for (int j = 0; j < 12; j++) {
            int idx = t + j * 256;
            reinterpret_cast<float4*>(orow + 192 + (idx >> 10) * 4096)[idx & 1023] = v[j];
        }
        if (t < 64) {
            const float* src;
            int c;
            if (t < 16)      { src = feas + b * 64  + 4 * t;        c = 4 * t; }
            else if (t < 48) { src = work + b * 128 + 4 * (t - 16); c = 64 + 4 * (t - 16); }
            else             { src = qa   + b * 64  + 4 * (t - 48); c = 12480 + 4 * (t - 48); }
            *reinterpret_cast<float4*>(orow + c) =
                *reinterpret_cast<const float4*>(src);
        }
    }
    __syncthreads();   // the ONLY barrier

    // ---- Phase 3: GEMM. B-frags: 1 coalesced LDG.64 per (kstep, nt).
    const int g    = lane >> 2;
    const int t4   = lane & 3;
    const int nb   = warp * 32;
    const int lrow = lane & 15;
    const int lcol = (lane >> 4) * 8;

    float acc[4][4][4];
    #pragma unroll
    for (int mt = 0; mt < 4; mt++)
        #pragma unroll
        for (int nt = 0; nt < 4; nt++)
            #pragma unroll
            for (int j = 0; j < 4; j++) acc[mt][nt][j] = 0.0f;

    const uint2* wf_base = g_Wfrag + warp * (16 * 4 * 32) + lane;

    #pragma unroll
    for (int ks = 0; ks < 16; ks++) {
        const int k0 = ks * 16;
        uint2 bf[4];
        #pragma unroll
        for (int nt = 0; nt < 4; nt++)
            bf[nt] = __ldg(wf_base + (ks * 4 + nt) * 32);
        #pragma unroll
        for (int mt = 0; mt < 4; mt++) {
            unsigned a0, a1, a2, a3;
            ldsm_x4(a0, a1, a2, a3, Xs + (mt * 16 + lrow) * XPAD + k0 + lcol);
            #pragma unroll
            for (int nt = 0; nt < 4; nt++)
                mma_bf16(acc[mt][nt][0], acc[mt][nt][1],
                         acc[mt][nt][2], acc[mt][nt][3],
                         a0, a1, a2, a3, bf[nt].x, bf[nt].y);
        }
    }

    // ---- Epilogue: tanh(.+bias), sum over M, shfl-reduce over g.
    float s0[4], s1[4];
    #pragma unroll
    for (int nt = 0; nt < 4; nt++) {
        const int c = nb + nt * 8 + 2 * t4;
        const float bz0 = __ldg(bias + c);
        const float bz1 = __ldg(bias + c + 1);
        float a = 0.f, bsum = 0.f;
        #pragma unroll
        for (int mt = 0; mt < 4; mt++) {
            a    += tanh_fast(acc[mt][nt][0] + bz0) + tanh_fast(acc[mt][nt][2] + bz0);
            bsum += tanh_fast(acc[mt][nt][1] + bz1) + tanh_fast(acc[mt][nt][3] + bz1);
        }
        s0[nt] = a; s1[nt] = bsum;
    }
    #pragma unroll
    for (int off = 4; off <= 16; off <<= 1) {
        #pragma unroll
        for (int nt = 0; nt < 4; nt++) {
            s0[nt] += __shfl_xor_sync(0xffffffffu, s0[nt], off);
            s1[nt] += __shfl_xor_sync(0xffffffffu, s1[nt], off);
        }
    }
    if (g == 0) {
        float* orow = out + (size_t)b * OUTW + COPYW;
        #pragma unroll
        for (int nt = 0; nt < 4; nt++) {
            const int c = nb + nt * 8 + 2 * t4;
            orow[c]     = s0[nt] * (1.0f / (float)PDIM);
            orow[c + 1] = s1[nt] * (1.0f / (float)PDIM);
        }
    }
}

// ---------------------------------------------------------------------------
extern "C" void kernel_launch(void* const* d_in, const int* in_sizes, int n_in,
                              void* d_out, int out_size) {
    const float* feas    = (const float*)d_in[0];
    const float* work    = (const float*)d_in[1];
    const float* known   = (const float*)d_in[2];
    const float* unknown = (const float*)d_in[3];
    const float* differ  = (const float*)d_in[4];
    const float* qa      = (const float*)d_in[5];
    const int*   nodes   = (const int*)d_in[6];
    const float* embed   = (const float*)d_in[7];
    const float* W       = (const float*)d_in[8];
    const float* bias    = (const float*)d_in[9];
    float* out = (float*)d_out;

    const int smem_bytes = PDIM * XPAD * sizeof(__nv_bfloat16);   // 33792 < 48KB

    wconv_kernel<<<64, 256>>>(W);
    fused_kernel<<<BDIM, 256, smem_bytes>>>(
        feas, work, known, unknown, differ, qa, nodes, embed, bias, out);
}